// round 16
// baseline (speedup 1.0000x reference)
#include <cuda_runtime.h>
#include <cuda_bf16.h>
#include <cstdint>
#include <math.h>

// Problem constants (fixed by setup_inputs): S=32768, D=512, I=8, T=8.
#define GQ   4096          // groups
#define DIM  512
#define BM   128           // CTA tile rows
#define BN   64            // CTA tile cols
#define BK   64
#define NKC  (DIM / BK)    // 8 k-chunks
#define NBJ  (GQ / BN)     // 64 col blocks
#define NBI  (GQ / BM)     // 32 row blocks
#define NTILE 1056         // sum_{bi} (64 - 2*bi)

// -------- device scratch (static; no runtime alloc allowed) -----------------
__device__ __align__(16) __nv_bfloat16 g_gfh[GQ * DIM];   // bf16 group means
__device__ float g_sq[GQ];                                // ||gf_i||^2
__device__ float g_psum_row[NBJ * GQ];                    // row-side partial sums
__device__ __align__(16) float g_ptop_row[NBJ * GQ * 4];  // row-side top-4
__device__ float g_psum_col[NBI * GQ];                    // col-side partial sums
__device__ __align__(16) float g_ptop_col[NBI * GQ * 4];  // col-side top-4

// -------- helpers ------------------------------------------------------------
__device__ __forceinline__ uint32_t smem_u32(const void* p) {
    uint32_t a;
    asm("{ .reg .u64 t; cvta.to.shared.u64 t, %1; cvt.u32.u64 %0, t; }"
        : "=r"(a) : "l"(p));
    return a;
}
#define SW128(o) ((o) ^ (((o) >> 3) & 0x70))

__device__ __forceinline__ void cp_async16(uint32_t saddr, const void* gaddr) {
    asm volatile("cp.async.cg.shared.global [%0], [%1], 16;"
                 :: "r"(saddr), "l"(gaddr));
}
__device__ __forceinline__ void cp_commit() {
    asm volatile("cp.async.commit_group;" ::: "memory");
}
template <int N>
__device__ __forceinline__ void cp_wait() {
    asm volatile("cp.async.wait_group %0;" :: "n"(N) : "memory");
}

__device__ __forceinline__ void ldsm_x4(uint32_t* r, uint32_t addr) {
    asm volatile("ldmatrix.sync.aligned.m8n8.x4.shared.b16 {%0,%1,%2,%3}, [%4];"
                 : "=r"(r[0]), "=r"(r[1]), "=r"(r[2]), "=r"(r[3]) : "r"(addr));
}
__device__ __forceinline__ void ldsm_x2(uint32_t* r, uint32_t addr) {
    asm volatile("ldmatrix.sync.aligned.m8n8.x2.shared.b16 {%0,%1}, [%2];"
                 : "=r"(r[0]), "=r"(r[1]) : "r"(addr));
}
__device__ __forceinline__ void mma16816(float* c, const uint32_t* a,
                                         const uint32_t* b) {
    asm volatile(
        "mma.sync.aligned.m16n8k16.row.col.f32.bf16.bf16.f32 "
        "{%0,%1,%2,%3}, {%4,%5,%6,%7}, {%8,%9}, {%0,%1,%2,%3};"
        : "+f"(c[0]), "+f"(c[1]), "+f"(c[2]), "+f"(c[3])
        : "r"(a[0]), "r"(a[1]), "r"(a[2]), "r"(a[3]), "r"(b[0]), "r"(b[1]));
}

__device__ __forceinline__ void ins4(float* t, float v) {
    if (v > t[3]) {
        if (v > t[2]) {
            t[3] = t[2];
            if (v > t[1]) {
                t[2] = t[1];
                if (v > t[0]) { t[1] = t[0]; t[0] = v; } else t[1] = v;
            } else t[2] = v;
        } else t[3] = v;
    }
}

// SMEM: 3 stages; stage s: A (16KB) @ s*24576, B (8KB) @ s*24576+16384.
#define STAGE_STRIDE 24576
#define SMEM_TOT     (3 * STAGE_STRIDE)     // 73728 -> 3 CTAs/SM (221184 <= carveout)
// epilogue reuse (stage 0): sqi@0(512) sqj@512(256) | rs@1024 [2][128] (1KB)
//   rt@2048 [2][128][4] (4KB) | cs@6144 [4][64] (1KB) | ct@7168 [4][64][4] (4KB)

// ======================= Kernel 1: group mean + sq ==========================
// 256 threads per block, 2 groups per block.
__global__ void __launch_bounds__(256) group_mean_kernel(const float* __restrict__ bf,
                                                         float* __restrict__ out) {
    int sub = threadIdx.x >> 7;            // group within block (0/1)
    int t = threadIdx.x & 127;             // column /4
    int g = blockIdx.x * 2 + sub;
    if (blockIdx.x == 0 && threadIdx.x == 0) out[0] = 0.f;  // zero loss accum
    const float4* p = reinterpret_cast<const float4*>(bf) + (size_t)g * 8 * 128 + t;
    float4 a = {0.f, 0.f, 0.f, 0.f};
#pragma unroll
    for (int r = 0; r < 8; r++) {
        float4 v = p[r * 128];
        a.x += v.x; a.y += v.y; a.z += v.z; a.w += v.w;
    }
    a.x *= 0.125f; a.y *= 0.125f; a.z *= 0.125f; a.w *= 0.125f;
    __nv_bfloat162 lo = __floats2bfloat162_rn(a.x, a.y);
    __nv_bfloat162 hi = __floats2bfloat162_rn(a.z, a.w);
    uint2 pk;
    pk.x = *reinterpret_cast<uint32_t*>(&lo);
    pk.y = *reinterpret_cast<uint32_t*>(&hi);
    *reinterpret_cast<uint2*>(g_gfh + (size_t)g * DIM + t * 4) = pk;

    float m2 = a.x * a.x + a.y * a.y + a.z * a.z + a.w * a.w;
#pragma unroll
    for (int o = 16; o; o >>= 1) m2 += __shfl_xor_sync(0xFFFFFFFFu, m2, o);
    __shared__ float ws[8];
    if ((threadIdx.x & 31) == 0) ws[threadIdx.x >> 5] = m2;
    __syncthreads();
    if (t == 0) {
        int b = sub * 4;
        g_sq[g] = ws[b] + ws[b + 1] + ws[b + 2] + ws[b + 3];
    }
}

// == Kernel 2: 128x64-tile triangular bf16 GEMM + two-sided epilogue =========
// 8 warps: warp_m = wid&3 (32 rows each), warp_n = wid>>2 (32 cols each).
// Tiles (bi,bj) with bj >= 2*bi. Straddlers (bj in {2bi,2bi+1}): row side only.
__global__ void __launch_bounds__(256, 3) poset_gemm_kernel() {
    extern __shared__ char smem[];
    uint32_t sbase = smem_u32(smem);
    int tid = threadIdx.x, wid = tid >> 5, lane = tid & 31;
    int warp_m = wid & 3;
    int warp_n = wid >> 2;

    // decode tile index -> (bi, bj), bj >= 2*bi
    int bi = 0, rem = blockIdx.x;
    while (rem >= NBJ - 2 * bi) { rem -= NBJ - 2 * bi; bi++; }
    int bj = 2 * bi + rem;
    int m0 = bi * BM;
    int n0 = bj * BN;
    bool colside = (bj >= 2 * bi + 2);   // non-straddler: also emit column side

    const uint4* gsrc = reinterpret_cast<const uint4*>(g_gfh);

    // loader: A = 1024 16B-units (4/thread), B = 512 units (2/thread)
    int l_row = tid >> 3, l_u = tid & 7;
    auto load_tile = [&](int stage, int kc) {
        uint32_t baseA = sbase + stage * STAGE_STRIDE;
        uint32_t baseB = baseA + 16384;
#pragma unroll
        for (int r = 0; r < 4; r++) {
            int row = l_row + r * 32;
            uint32_t soff = SW128(row * 128 + l_u * 16);
            cp_async16(baseA + soff, gsrc + (size_t)(m0 + row) * 64 + kc * 8 + l_u);
        }
#pragma unroll
        for (int r = 0; r < 2; r++) {
            int row = l_row + r * 32;
            uint32_t soff = SW128(row * 128 + l_u * 16);
            cp_async16(baseB + soff, gsrc + (size_t)(n0 + row) * 64 + kc * 8 + l_u);
        }
        cp_commit();
    };

    float acc[2][4][4];
#pragma unroll
    for (int mf = 0; mf < 2; mf++)
#pragma unroll
        for (int nf = 0; nf < 4; nf++)
#pragma unroll
            for (int q = 0; q < 4; q++) acc[mf][nf][q] = 0.f;

    // lean ldsm addressing:
    // SW128((row+d)*128 + ks*32 + kb) == (row+d)*128 + ((kb ^ ((row&7)<<4)) ^ ks*32)
    int a_row = warp_m * 32 + (lane & 15);
    uint32_t pA = (((uint32_t)lane >> 4) << 4) ^ (((uint32_t)a_row & 7) << 4);
    uint32_t aterm0 = (uint32_t)a_row * 128;          // + mf*2048
    int b_row = warp_n * 32 + (lane & 7);
    uint32_t pB = ((((uint32_t)lane >> 3) & 1) << 4) ^ (((uint32_t)lane & 7) << 4);
    uint32_t bterm0 = (uint32_t)b_row * 128;          // + nf*1024

    load_tile(0, 0);
    load_tile(1, 1);

#pragma unroll 1
    for (int kc = 0; kc < NKC; kc++) {
        if (kc < NKC - 1) cp_wait<1>(); else cp_wait<0>();
        __syncthreads();
        if (kc + 2 < NKC) load_tile((kc + 2) % 3, kc + 2);

        uint32_t baseA = sbase + (kc % 3) * STAGE_STRIDE;
        uint32_t aA = baseA + aterm0;
        uint32_t aB = baseA + 16384 + bterm0;

#pragma unroll
        for (int ks = 0; ks < 4; ks++) {
            uint32_t k32 = (uint32_t)ks * 32;
            uint32_t a_reg[2][4], b_reg[4][2];
#pragma unroll
            for (int mf = 0; mf < 2; mf++)
                ldsm_x4(a_reg[mf], aA + mf * 2048 + (pA ^ k32));
#pragma unroll
            for (int nf = 0; nf < 4; nf++)
                ldsm_x2(b_reg[nf], aB + nf * 1024 + (pB ^ k32));
#pragma unroll
            for (int mf = 0; mf < 2; mf++)
#pragma unroll
                for (int nf = 0; nf < 4; nf++)
                    mma16816(acc[mf][nf], a_reg[mf], b_reg[nf]);
        }
    }
    __syncthreads();   // mainloop fully done before SMEM reuse

    // ------------------------- fused two-sided epilogue ---------------------
    float* s_sqi = (float*)(smem);           // 128
    float* s_sqj = (float*)(smem + 512);     // 64
    float* s_rs  = (float*)(smem + 1024);    // [2 warp_n][128 rows]
    float* s_rt  = (float*)(smem + 2048);    // [2 warp_n][128][4]
    float* s_cs  = (float*)(smem + 6144);    // [4 warp_m][64 cols]
    float* s_ct  = (float*)(smem + 7168);    // [4 warp_m][64][4]

    if (tid < 128) s_sqi[tid] = g_sq[m0 + tid];
    else if (tid < 192) s_sqj[tid - 128] = g_sq[n0 + tid - 128];
    __syncthreads();

    int r_l = lane >> 2;
    int c_l = (lane & 3) * 2;
    float rsum[4];
    float rtop[4][4];
#pragma unroll
    for (int r = 0; r < 4; r++) {
        rsum[r] = 0.f;
#pragma unroll
        for (int q = 0; q < 4; q++) rtop[r][q] = 0.f;
    }

#pragma unroll
    for (int nf = 0; nf < 4; nf++) {
        int colbase = warp_n * 32 + nf * 8 + c_l;
        float sj0 = s_sqj[colbase], sj1 = s_sqj[colbase + 1];
        int j0 = n0 + colbase, j1 = j0 + 1;
        float csum[2] = {0.f, 0.f};
        float ctop[2][4] = {{0.f,0.f,0.f,0.f},{0.f,0.f,0.f,0.f}};
#pragma unroll
        for (int mf = 0; mf < 2; mf++) {
            int row0 = warp_m * 32 + mf * 16 + r_l;
            float si0 = s_sqi[row0], si1 = s_sqi[row0 + 8];
            int i0 = m0 + row0, i1 = i0 + 8;
#pragma unroll
            for (int q = 0; q < 4; q++) {
                float si = (q < 2) ? si0 : si1;
                float sj = (q & 1) ? sj1 : sj0;
                int ii = (q < 2) ? i0 : i1;
                int jj = (q & 1) ? j1 : j0;
                int r  = mf * 2 + (q >> 1);
                float d2 = fmaf(-2.0f, acc[mf][nf][q], si + sj);
                d2 = fmaxf(d2, 1e-12f);
                float e = __expf(-0.125f * sqrtf(d2));
                bool cross = ((ii ^ jj) & 7) != 0;
                rsum[r] += e;
                csum[q & 1] += e;
                if (cross) { ins4(rtop[r], e); ins4(ctop[q & 1], e); }
            }
        }
        // merge columns across the 8 lane-groups (lane>>2) sharing each column
        if (colside) {
#pragma unroll
            for (int off = 4; off <= 16; off <<= 1) {
#pragma unroll
                for (int p = 0; p < 2; p++) {
                    csum[p] += __shfl_xor_sync(0xFFFFFFFFu, csum[p], off);
                    float u0 = __shfl_xor_sync(0xFFFFFFFFu, ctop[p][0], off);
                    float u1 = __shfl_xor_sync(0xFFFFFFFFu, ctop[p][1], off);
                    float u2 = __shfl_xor_sync(0xFFFFFFFFu, ctop[p][2], off);
                    float u3 = __shfl_xor_sync(0xFFFFFFFFu, ctop[p][3], off);
                    ins4(ctop[p], u0); ins4(ctop[p], u1);
                    ins4(ctop[p], u2); ins4(ctop[p], u3);
                }
            }
            if (lane < 4) {
#pragma unroll
                for (int p = 0; p < 2; p++) {
                    int col_l = warp_n * 32 + nf * 8 + lane * 2 + p;
                    s_cs[warp_m * 64 + col_l] = csum[p];
#pragma unroll
                    for (int q = 0; q < 4; q++)
                        s_ct[(warp_m * 64 + col_l) * 4 + q] = ctop[p][q];
                }
            }
        }
    }

    // merge rows across the 4 lanes (lane&3) that share each row
#pragma unroll
    for (int off = 1; off <= 2; off <<= 1) {
#pragma unroll
        for (int r = 0; r < 4; r++) {
            rsum[r] += __shfl_xor_sync(0xFFFFFFFFu, rsum[r], off);
            float t0 = __shfl_xor_sync(0xFFFFFFFFu, rtop[r][0], off);
            float t1 = __shfl_xor_sync(0xFFFFFFFFu, rtop[r][1], off);
            float t2 = __shfl_xor_sync(0xFFFFFFFFu, rtop[r][2], off);
            float t3 = __shfl_xor_sync(0xFFFFFFFFu, rtop[r][3], off);
            ins4(rtop[r], t0); ins4(rtop[r], t1);
            ins4(rtop[r], t2); ins4(rtop[r], t3);
        }
    }
    if ((lane & 3) == 0) {
        int rb = lane >> 2;
#pragma unroll
        for (int mf = 0; mf < 2; mf++)
#pragma unroll
            for (int h = 0; h < 2; h++) {
                int r = mf * 2 + h;
                int row_l = warp_m * 32 + mf * 16 + h * 8 + rb;
                s_rs[warp_n * 128 + row_l] = rsum[r];
#pragma unroll
                for (int q = 0; q < 4; q++)
                    s_rt[(warp_n * 128 + row_l) * 4 + q] = rtop[r][q];
            }
    }
    __syncthreads();

    if (tid < 128) {
        // row side -> slot bj
        float all = s_rs[tid] + s_rs[128 + tid];
        float top[4] = {0.f, 0.f, 0.f, 0.f};
#pragma unroll
        for (int wn = 0; wn < 2; wn++)
#pragma unroll
            for (int q = 0; q < 4; q++)
                ins4(top, s_rt[(wn * 128 + tid) * 4 + q]);
        int i = m0 + tid;
        g_psum_row[bj * GQ + i] = all;
#pragma unroll
        for (int q = 0; q < 4; q++)
            g_ptop_row[((size_t)bj * GQ + i) * 4 + q] = top[q];
    } else if (tid < 192 && colside) {
        // column side -> slot bi
        int t2 = tid - 128;
        float all = 0.f;
        float top[4] = {0.f, 0.f, 0.f, 0.f};
#pragma unroll
        for (int wm = 0; wm < 4; wm++) {
            all += s_cs[wm * 64 + t2];
#pragma unroll
            for (int q = 0; q < 4; q++)
                ins4(top, s_ct[(wm * 64 + t2) * 4 + q]);
        }
        int j = n0 + t2;
        g_psum_col[bi * GQ + j] = all;
#pragma unroll
        for (int q = 0; q < 4; q++)
            g_ptop_col[((size_t)bi * GQ + j) * 4 + q] = top[q];
    }
}

// ====== Kernel 3: per-row merge + loss + atomic mean accumulation ===========
__global__ void __launch_bounds__(256) finalize_rows(float* __restrict__ out) {
    int i = blockIdx.x * 256 + threadIdx.x;   // one row per thread
    int bi128 = i >> 7;
    int b64   = i >> 6;
    float all = 0.f;
    float top[4] = {0.f, 0.f, 0.f, 0.f};
#pragma unroll 2
    for (int bj = 2 * bi128; bj < NBJ; bj++) {
        all += g_psum_row[bj * GQ + i];
        float4 t = *reinterpret_cast<const float4*>(&g_ptop_row[((size_t)bj * GQ + i) * 4]);
        ins4(top, t.x); ins4(top, t.y); ins4(top, t.z); ins4(top, t.w);
    }
#pragma unroll 2
    for (int c = 0; c < (b64 >> 1); c++) {
        all += g_psum_col[c * GQ + i];
        float4 t = *reinterpret_cast<const float4*>(&g_ptop_col[((size_t)c * GQ + i) * 4]);
        ins4(top, t.x); ins4(top, t.y); ins4(top, t.z); ins4(top, t.w);
    }
    float near = top[0] + top[1] + top[2] + top[3];
    float acc = (logf(all) - logf(near)) * (1.0f / (float)GQ);

#pragma unroll
    for (int o = 16; o; o >>= 1) acc += __shfl_xor_sync(0xFFFFFFFFu, acc, o);
    __shared__ float ws[8];
    if ((threadIdx.x & 31) == 0) ws[threadIdx.x >> 5] = acc;
    __syncthreads();
    if (threadIdx.x == 0) {
        float s = 0.f;
#pragma unroll
        for (int w = 0; w < 8; w++) s += ws[w];
        atomicAdd(out, s);
    }
}

// ============================== launch ======================================
extern "C" void kernel_launch(void* const* d_in, const int* in_sizes, int n_in,
                              void* d_out, int out_size) {
    const float* bf = (const float*)d_in[0];
    (void)in_sizes; (void)n_in; (void)out_size;

    cudaFuncSetAttribute(poset_gemm_kernel,
                         cudaFuncAttributeMaxDynamicSharedMemorySize, SMEM_TOT);

    group_mean_kernel<<<GQ / 2, 256>>>(bf, (float*)d_out);
    poset_gemm_kernel<<<NTILE, 256, SMEM_TOT>>>();
    finalize_rows<<<GQ / 256, 256>>>((float*)d_out);
}

// round 17
// speedup vs baseline: 1.3653x; 1.3653x over previous
#include <cuda_runtime.h>
#include <cuda_bf16.h>
#include <cstdint>
#include <math.h>

// Problem constants (fixed by setup_inputs): S=32768, D=512, I=8, T=8.
#define GQ   4096          // groups
#define DIM  512
#define BM   128
#define BN   128
#define BK   64
#define NKC  (DIM / BK)    // 8 k-chunks
#define NCH  (GQ / BN)     // 32 blocks per dim
#define NTILE (NCH * (NCH + 1) / 2)   // 528 triangular tiles

// -------- device scratch (static; no runtime alloc allowed) -----------------
__device__ __align__(16) __nv_bfloat16 g_gfh[GQ * DIM];  // bf16 group means
__device__ float g_sq[GQ];                               // ||gf_i||^2
__device__ float g_psum[NCH * GQ];                       // partial row sums
__device__ __align__(16) float g_ptop[NCH * GQ * 4];     // partial top-4

// -------- helpers ------------------------------------------------------------
__device__ __forceinline__ uint32_t smem_u32(const void* p) {
    uint32_t a;
    asm("{ .reg .u64 t; cvta.to.shared.u64 t, %1; cvt.u32.u64 %0, t; }"
        : "=r"(a) : "l"(p));
    return a;
}
#define SW128(o) ((o) ^ (((o) >> 3) & 0x70))

__device__ __forceinline__ void cp_async16(uint32_t saddr, const void* gaddr) {
    asm volatile("cp.async.cg.shared.global [%0], [%1], 16;"
                 :: "r"(saddr), "l"(gaddr));
}
__device__ __forceinline__ void cp_commit() {
    asm volatile("cp.async.commit_group;" ::: "memory");
}
template <int N>
__device__ __forceinline__ void cp_wait() {
    asm volatile("cp.async.wait_group %0;" :: "n"(N) : "memory");
}

__device__ __forceinline__ void ldsm_x4(uint32_t* r, uint32_t addr) {
    asm volatile("ldmatrix.sync.aligned.m8n8.x4.shared.b16 {%0,%1,%2,%3}, [%4];"
                 : "=r"(r[0]), "=r"(r[1]), "=r"(r[2]), "=r"(r[3]) : "r"(addr));
}
__device__ __forceinline__ void ldsm_x2(uint32_t* r, uint32_t addr) {
    asm volatile("ldmatrix.sync.aligned.m8n8.x2.shared.b16 {%0,%1}, [%2];"
                 : "=r"(r[0]), "=r"(r[1]) : "r"(addr));
}
__device__ __forceinline__ void mma16816(float* c, const uint32_t* a,
                                         const uint32_t* b) {
    asm volatile(
        "mma.sync.aligned.m16n8k16.row.col.f32.bf16.bf16.f32 "
        "{%0,%1,%2,%3}, {%4,%5,%6,%7}, {%8,%9}, {%0,%1,%2,%3};"
        : "+f"(c[0]), "+f"(c[1]), "+f"(c[2]), "+f"(c[3])
        : "r"(a[0]), "r"(a[1]), "r"(a[2]), "r"(a[3]), "r"(b[0]), "r"(b[1]));
}

__device__ __forceinline__ void ins4(float* t, float v) {
    if (v > t[3]) {
        if (v > t[2]) {
            t[3] = t[2];
            if (v > t[1]) {
                t[2] = t[1];
                if (v > t[0]) { t[1] = t[0]; t[0] = v; } else t[1] = v;
            } else t[2] = v;
        } else t[3] = v;
    }
}

// SMEM: 3 pipeline stages; stage s: A @ s*32768, B @ s*32768+16384.
#define STAGE_STRIDE 32768
#define SMEM_TOT     (3 * STAGE_STRIDE)     // 98304
// epilogue reuse: sqi@0(512) sqj@512(512) | rs@1024 [4][128] | rt@3072 [4][128][4]
//   cs@11264 [2][128] | ct@12288 [2][128][4] (ends 16384)
//   e-matrix @16384: [128][132] f32 = 67584 bytes (ends 83968 < 98304)
#define E_STRIDE 132

// ======================= Kernel 1: group mean + sq ==========================
// 256 threads per block, 2 groups per block.
__global__ void __launch_bounds__(256) group_mean_kernel(const float* __restrict__ bf,
                                                         float* __restrict__ out) {
    int sub = threadIdx.x >> 7;
    int t = threadIdx.x & 127;
    int g = blockIdx.x * 2 + sub;
    if (blockIdx.x == 0 && threadIdx.x == 0) out[0] = 0.f;  // zero loss accum
    const float4* p = reinterpret_cast<const float4*>(bf) + (size_t)g * 8 * 128 + t;
    float4 a = {0.f, 0.f, 0.f, 0.f};
#pragma unroll
    for (int r = 0; r < 8; r++) {
        float4 v = p[r * 128];
        a.x += v.x; a.y += v.y; a.z += v.z; a.w += v.w;
    }
    a.x *= 0.125f; a.y *= 0.125f; a.z *= 0.125f; a.w *= 0.125f;
    __nv_bfloat162 lo = __floats2bfloat162_rn(a.x, a.y);
    __nv_bfloat162 hi = __floats2bfloat162_rn(a.z, a.w);
    uint2 pk;
    pk.x = *reinterpret_cast<uint32_t*>(&lo);
    pk.y = *reinterpret_cast<uint32_t*>(&hi);
    *reinterpret_cast<uint2*>(g_gfh + (size_t)g * DIM + t * 4) = pk;

    float m2 = a.x * a.x + a.y * a.y + a.z * a.z + a.w * a.w;
#pragma unroll
    for (int o = 16; o; o >>= 1) m2 += __shfl_xor_sync(0xFFFFFFFFu, m2, o);
    __shared__ float ws[8];
    if ((threadIdx.x & 31) == 0) ws[threadIdx.x >> 5] = m2;
    __syncthreads();
    if (t == 0) {
        int b = sub * 4;
        g_sq[g] = ws[b] + ws[b + 1] + ws[b + 2] + ws[b + 3];
    }
}

// == Kernel 2: triangular bf16 GEMM + low-pressure two-pass epilogue =========
__global__ void __launch_bounds__(256, 2) poset_gemm_kernel() {
    extern __shared__ char smem[];
    uint32_t sbase = smem_u32(smem);
    int tid = threadIdx.x, wid = tid >> 5, lane = tid & 31;
    int warp_m = wid & 1;         // 2 warps along M (64 rows each)
    int warp_n = wid >> 1;        // 4 warps along N (32 cols each)

    // decode triangular tile index -> (bi, bj), bi <= bj
    int bi = 0, rem = blockIdx.x;
    while (rem >= NCH - bi) { rem -= NCH - bi; bi++; }
    int bj = bi + rem;
    int m0 = bi * BM;
    int n0 = bj * BN;
    bool offdiag = (bi != bj);

    const uint4* gsrc = reinterpret_cast<const uint4*>(g_gfh);

    // loader thread mapping: 4 iters of 256 threads cover 1024 16B units
    int l_row = tid >> 3, l_u = tid & 7;
    auto load_tile = [&](int stage, int kc) {
        uint32_t baseA = sbase + stage * STAGE_STRIDE;
        uint32_t baseB = baseA + 16384;
#pragma unroll
        for (int r = 0; r < 4; r++) {
            int row = l_row + r * 32;
            uint32_t soff = SW128(row * 128 + l_u * 16);
            cp_async16(baseA + soff, gsrc + (size_t)(m0 + row) * 64 + kc * 8 + l_u);
            cp_async16(baseB + soff, gsrc + (size_t)(n0 + row) * 64 + kc * 8 + l_u);
        }
        cp_commit();
    };

    float acc[4][4][4];
#pragma unroll
    for (int mf = 0; mf < 4; mf++)
#pragma unroll
        for (int nf = 0; nf < 4; nf++)
#pragma unroll
            for (int q = 0; q < 4; q++) acc[mf][nf][q] = 0.f;

    // lean ldsm addressing:
    // SW128((row+d)*128 + ks*32 + kb) == (row+d)*128 + ((kb ^ ((row&7)<<4)) ^ ks*32)
    int a_row = warp_m * 64 + (lane & 15);
    uint32_t pA = (((uint32_t)lane >> 4) << 4) ^ (((uint32_t)a_row & 7) << 4);
    uint32_t aterm0 = (uint32_t)a_row * 128;          // + mf*2048
    int b_row = warp_n * 32 + (lane & 7);
    uint32_t pB = ((((uint32_t)lane >> 3) & 1) << 4) ^ (((uint32_t)lane & 7) << 4);
    uint32_t bterm0 = (uint32_t)b_row * 128;          // + nf*1024

    load_tile(0, 0);
    load_tile(1, 1);

#pragma unroll 1
    for (int kc = 0; kc < NKC; kc++) {
        if (kc < NKC - 1) cp_wait<1>(); else cp_wait<0>();
        __syncthreads();
        if (kc + 2 < NKC) load_tile((kc + 2) % 3, kc + 2);

        uint32_t baseA = sbase + (kc % 3) * STAGE_STRIDE;
        uint32_t aA = baseA + aterm0;
        uint32_t aB = baseA + 16384 + bterm0;

#pragma unroll
        for (int ks = 0; ks < 4; ks++) {
            uint32_t k32 = (uint32_t)ks * 32;
            uint32_t a_reg[4][4], b_reg[4][2];
#pragma unroll
            for (int mf = 0; mf < 4; mf++)
                ldsm_x4(a_reg[mf], aA + mf * 2048 + (pA ^ k32));
#pragma unroll
            for (int nf = 0; nf < 4; nf++)
                ldsm_x2(b_reg[nf], aB + nf * 1024 + (pB ^ k32));
#pragma unroll
            for (int mf = 0; mf < 4; mf++)
#pragma unroll
                for (int nf = 0; nf < 4; nf++)
                    mma16816(acc[mf][nf], a_reg[mf], b_reg[nf]);
        }
    }
    __syncthreads();   // mainloop fully done before SMEM reuse

    // ------------------ two-pass epilogue (low register pressure) -----------
    float* s_sqi = (float*)(smem);           // 128 f32
    float* s_sqj = (float*)(smem + 512);     // 128 f32
    float* s_rs  = (float*)(smem + 1024);    // [4 warp_n][128 rows]
    float* s_rt  = (float*)(smem + 3072);    // [4 warp_n][128][4]
    float* s_cs  = (float*)(smem + 11264);   // [2 half][128 cols]
    float* s_ct  = (float*)(smem + 12288);   // [2 half][128][4]
    float* s_e   = (float*)(smem + 16384);   // [128][E_STRIDE]

    if (tid < 128) s_sqi[tid] = g_sq[m0 + tid];
    else           s_sqj[tid - 128] = g_sq[n0 + tid - 128];
    __syncthreads();

    int r_l = lane >> 2;
    int c_l = (lane & 3) * 2;

    // ---- pass 1: compute e, store to SMEM, accumulate ROW stats only ------
#pragma unroll
    for (int mf = 0; mf < 4; mf++) {
        int row0 = warp_m * 64 + mf * 16 + r_l;
        float si0 = s_sqi[row0], si1 = s_sqi[row0 + 8];
        int i0 = m0 + row0, i1 = i0 + 8;
        float sum2[2] = {0.f, 0.f};
        float top2[2][4] = {{0.f,0.f,0.f,0.f},{0.f,0.f,0.f,0.f}};
#pragma unroll
        for (int nf = 0; nf < 4; nf++) {
            int colbase = warp_n * 32 + nf * 8 + c_l;
            float sj0 = s_sqj[colbase], sj1 = s_sqj[colbase + 1];
            int j0 = n0 + colbase, j1 = j0 + 1;
#pragma unroll
            for (int q = 0; q < 4; q++) {
                float si = (q < 2) ? si0 : si1;
                float sj = (q & 1) ? sj1 : sj0;
                int ii = (q < 2) ? i0 : i1;
                int jj = (q & 1) ? j1 : j0;
                int h  = q >> 1;
                float d2 = fmaf(-2.0f, acc[mf][nf][q], si + sj);
                d2 = fmaxf(d2, 1e-12f);
                float e = __expf(-0.125f * sqrtf(d2));
                int row_l = row0 + h * 8;
                int col_l = colbase + (q & 1);
                s_e[row_l * E_STRIDE + col_l] = e;
                sum2[h] += e;
                if (((ii ^ jj) & 7) != 0) ins4(top2[h], e);
            }
        }
        // merge across the 4 lanes (lane&3) sharing each row
#pragma unroll
        for (int off = 1; off <= 2; off <<= 1) {
#pragma unroll
            for (int h = 0; h < 2; h++) {
                sum2[h] += __shfl_xor_sync(0xFFFFFFFFu, sum2[h], off);
                float t0 = __shfl_xor_sync(0xFFFFFFFFu, top2[h][0], off);
                float t1 = __shfl_xor_sync(0xFFFFFFFFu, top2[h][1], off);
                float t2 = __shfl_xor_sync(0xFFFFFFFFu, top2[h][2], off);
                float t3 = __shfl_xor_sync(0xFFFFFFFFu, top2[h][3], off);
                ins4(top2[h], t0); ins4(top2[h], t1);
                ins4(top2[h], t2); ins4(top2[h], t3);
            }
        }
        if ((lane & 3) == 0) {
            int rb = lane >> 2;
#pragma unroll
            for (int h = 0; h < 2; h++) {
                int row_l = warp_m * 64 + mf * 16 + h * 8 + rb;
                s_rs[warp_n * 128 + row_l] = sum2[h];
#pragma unroll
                for (int q = 0; q < 4; q++)
                    s_rt[(warp_n * 128 + row_l) * 4 + q] = top2[h][q];
            }
        }
    }
    __syncthreads();

    // ---- pass 2: column stats from SMEM e-matrix (offdiag only) ------------
    if (offdiag) {
        int t2 = tid & 127;        // column
        int h  = tid >> 7;         // row half: rows [h*64, h*64+64)
        int j  = n0 + t2;
        float csum = 0.f;
        float ctop[4] = {0.f, 0.f, 0.f, 0.f};
        const float* ecol = s_e + (size_t)(h * 64) * E_STRIDE + t2;
#pragma unroll 8
        for (int r = 0; r < 64; r++) {
            float e = ecol[r * E_STRIDE];
            csum += e;
            int i = m0 + h * 64 + r;
            if (((i ^ j) & 7) != 0) ins4(ctop, e);
        }
        s_cs[h * 128 + t2] = csum;
#pragma unroll
        for (int q = 0; q < 4; q++) s_ct[(h * 128 + t2) * 4 + q] = ctop[q];
    }
    __syncthreads();

    // ---- global writes ------------------------------------------------------
    if (tid < 128) {
        // row side -> slot bj
        float all = 0.f;
        float top[4] = {0.f, 0.f, 0.f, 0.f};
#pragma unroll
        for (int wn = 0; wn < 4; wn++) {
            all += s_rs[wn * 128 + tid];
#pragma unroll
            for (int q = 0; q < 4; q++)
                ins4(top, s_rt[(wn * 128 + tid) * 4 + q]);
        }
        int i = m0 + tid;
        g_psum[bj * GQ + i] = all;
#pragma unroll
        for (int q = 0; q < 4; q++)
            g_ptop[((size_t)bj * GQ + i) * 4 + q] = top[q];
    } else if (offdiag) {
        // column side -> slot bi
        int t2 = tid - 128;
        float all = s_cs[t2] + s_cs[128 + t2];
        float top[4] = {0.f, 0.f, 0.f, 0.f};
#pragma unroll
        for (int hh = 0; hh < 2; hh++)
#pragma unroll
            for (int q = 0; q < 4; q++)
                ins4(top, s_ct[(hh * 128 + t2) * 4 + q]);
        int j = n0 + t2;
        g_psum[bi * GQ + j] = all;
#pragma unroll
        for (int q = 0; q < 4; q++)
            g_ptop[((size_t)bi * GQ + j) * 4 + q] = top[q];
    }
}

// ====== Kernel 3: per-row merge + loss + atomic mean accumulation ===========
__global__ void __launch_bounds__(256) finalize_rows(float* __restrict__ out) {
    int i = blockIdx.x * 256 + threadIdx.x;   // one row per thread
    float all = 0.f;
    float top[4] = {0.f, 0.f, 0.f, 0.f};
#pragma unroll 4
    for (int c = 0; c < NCH; c++) {
        all += g_psum[c * GQ + i];
        float4 t = *reinterpret_cast<const float4*>(&g_ptop[((size_t)c * GQ + i) * 4]);
        ins4(top, t.x); ins4(top, t.y); ins4(top, t.z); ins4(top, t.w);
    }
    float near = top[0] + top[1] + top[2] + top[3];
    float acc = (logf(all) - logf(near)) * (1.0f / (float)GQ);

#pragma unroll
    for (int o = 16; o; o >>= 1) acc += __shfl_xor_sync(0xFFFFFFFFu, acc, o);
    __shared__ float ws[8];
    if ((threadIdx.x & 31) == 0) ws[threadIdx.x >> 5] = acc;
    __syncthreads();
    if (threadIdx.x == 0) {
        float s = 0.f;
#pragma unroll
        for (int w = 0; w < 8; w++) s += ws[w];
        atomicAdd(out, s);
    }
}

// ============================== launch ======================================
extern "C" void kernel_launch(void* const* d_in, const int* in_sizes, int n_in,
                              void* d_out, int out_size) {
    const float* bf = (const float*)d_in[0];
    (void)in_sizes; (void)n_in; (void)out_size;

    cudaFuncSetAttribute(poset_gemm_kernel,
                         cudaFuncAttributeMaxDynamicSharedMemorySize, SMEM_TOT);

    group_mean_kernel<<<GQ / 2, 256>>>(bf, (float*)d_out);
    poset_gemm_kernel<<<NTILE, 256, SMEM_TOT>>>();
    finalize_rows<<<GQ / 256, 256>>>((float*)d_out);
}